// round 1
// baseline (speedup 1.0000x reference)
#include <cuda_runtime.h>

// VQ: encodings (16384, 64) fp32, codebook (8192, 64) fp32.
// out[q] = codebook[argmin_k ||enc[q] - cb[k]||^2]  (first-min index on ties)
//
// Fused distance + argmin + gather. Monotone metric: m = ||c||^2 - 2 x.c
// (||x||^2 is constant per query and dropped).

#define N_Q   16384
#define DIMS  64
#define K_CB  8192
#define QT    64      // queries per block
#define KT    64      // codewords per iteration
#define STR   68      // padded smem row length (floats), keeps float4 alignment

__device__ float g_csq[K_CB];   // codeword squared norms (scratch, no alloc)

// ---------------- c^2 precompute: one warp per codebook row ----------------
__global__ void csq_kernel(const float* __restrict__ cb) {
    int row  = blockIdx.x * 8 + (threadIdx.x >> 5);
    int lane = threadIdx.x & 31;
    float v0 = cb[row * DIMS + lane];
    float v1 = cb[row * DIMS + 32 + lane];
    float s  = v0 * v0 + v1 * v1;
    #pragma unroll
    for (int off = 16; off; off >>= 1)
        s += __shfl_xor_sync(0xffffffffu, s, off);
    if (lane == 0) g_csq[row] = s;
}

// ---------------- main fused kernel ----------------
__global__ __launch_bounds__(256, 2)
void vq_kernel(const float* __restrict__ enc,
               const float* __restrict__ cb,
               float* __restrict__ out)
{
    __shared__ float q_sm[DIMS][STR];   // transposed query tile [d][q]
    __shared__ float c_sm[DIMS][STR];   // transposed codeword tile [d][k]
    __shared__ float csq_sm[KT];
    __shared__ int   bidx_sm[QT];

    const int tid = threadIdx.x;
    const int tx  = tid & 15;           // codeword sub-tile (4 codewords)
    const int ty  = tid >> 4;           // query sub-tile   (4 queries)
    const int qbase = blockIdx.x * QT;

    const float4* enc4 = (const float4*)enc;
    const float4* cb4  = (const float4*)cb;

    // Load query tile once, transposed into smem.
    #pragma unroll
    for (int it = 0; it < 4; ++it) {
        int idx  = tid + it * 256;          // 0..1023
        int r    = idx >> 4;                // query row 0..63
        int quad = idx & 15;                // float4 chunk 0..15
        float4 v = enc4[(qbase + r) * 16 + quad];
        int d0 = quad * 4;
        q_sm[d0 + 0][r] = v.x;
        q_sm[d0 + 1][r] = v.y;
        q_sm[d0 + 2][r] = v.z;
        q_sm[d0 + 3][r] = v.w;
    }

    float bestm[4];
    int   besti[4];
    #pragma unroll
    for (int i = 0; i < 4; ++i) { bestm[i] = 3.4e38f; besti[i] = 0; }

    for (int kb = 0; kb < K_CB; kb += KT) {
        __syncthreads();   // protect c_sm from previous iteration's readers

        // Load codeword tile transposed.
        #pragma unroll
        for (int it = 0; it < 4; ++it) {
            int idx  = tid + it * 256;
            int r    = idx >> 4;
            int quad = idx & 15;
            float4 v = cb4[(kb + r) * 16 + quad];
            int d0 = quad * 4;
            c_sm[d0 + 0][r] = v.x;
            c_sm[d0 + 1][r] = v.y;
            c_sm[d0 + 2][r] = v.z;
            c_sm[d0 + 3][r] = v.w;
        }
        if (tid < 16) {
            float4 s = *(const float4*)&g_csq[kb + tid * 4];
            *(float4*)&csq_sm[tid * 4] = s;
        }
        __syncthreads();

        // 4x4 register tile of dot products over the full D=64 reduction.
        float acc[4][4];
        #pragma unroll
        for (int i = 0; i < 4; ++i)
            #pragma unroll
            for (int j = 0; j < 4; ++j) acc[i][j] = 0.f;

        #pragma unroll
        for (int d = 0; d < DIMS; ++d) {
            float4 qv = *(const float4*)&q_sm[d][ty * 4];
            float4 cv = *(const float4*)&c_sm[d][tx * 4];
            float qa[4] = {qv.x, qv.y, qv.z, qv.w};
            float ca[4] = {cv.x, cv.y, cv.z, cv.w};
            #pragma unroll
            for (int i = 0; i < 4; ++i)
                #pragma unroll
                for (int j = 0; j < 4; ++j)
                    acc[i][j] = fmaf(qa[i], ca[j], acc[i][j]);
        }

        // Update running argmin. k ascending within a thread, so strict '<'
        // preserves first-min semantics.
        float4 cs4 = *(const float4*)&csq_sm[tx * 4];
        float cs[4] = {cs4.x, cs4.y, cs4.z, cs4.w};
        #pragma unroll
        for (int j = 0; j < 4; ++j) {
            int k = kb + tx * 4 + j;
            #pragma unroll
            for (int i = 0; i < 4; ++i) {
                float m = fmaf(-2.f, acc[i][j], cs[j]);
                if (m < bestm[i]) { bestm[i] = m; besti[i] = k; }
            }
        }
    }

    // Reduce across the 16 codeword-axis threads (same half-warp: offsets <=8).
    #pragma unroll
    for (int off = 8; off; off >>= 1) {
        #pragma unroll
        for (int i = 0; i < 4; ++i) {
            float om = __shfl_xor_sync(0xffffffffu, bestm[i], off);
            int   oi = __shfl_xor_sync(0xffffffffu, besti[i], off);
            if (om < bestm[i] || (om == bestm[i] && oi < besti[i])) {
                bestm[i] = om; besti[i] = oi;
            }
        }
    }
    if (tx == 0) {
        #pragma unroll
        for (int i = 0; i < 4; ++i) bidx_sm[ty * 4 + i] = besti[i];
    }
    __syncthreads();

    // Coalesced gather: out[q] = codebook[best_idx[q]].
    float4* out4 = (float4*)out;
    #pragma unroll
    for (int it = 0; it < 4; ++it) {
        int idx  = tid + it * 256;
        int q    = idx >> 4;
        int quad = idx & 15;
        int k    = bidx_sm[q];
        out4[(qbase + q) * 16 + quad] = cb4[k * 16 + quad];
    }
}

extern "C" void kernel_launch(void* const* d_in, const int* in_sizes, int n_in,
                              void* d_out, int out_size) {
    // metadata order: encodings (1048576 floats), codebook (524288 floats).
    // Select by size defensively.
    const float* enc = (const float*)d_in[0];
    const float* cb  = (const float*)d_in[1];
    if (n_in >= 2 && in_sizes[0] == K_CB * DIMS && in_sizes[1] == N_Q * DIMS) {
        enc = (const float*)d_in[1];
        cb  = (const float*)d_in[0];
    }
    float* out = (float*)d_out;

    csq_kernel<<<K_CB / 8, 256>>>(cb);
    vq_kernel<<<N_Q / QT, 256>>>(enc, cb, out);
}

// round 4
// speedup vs baseline: 2.5960x; 2.5960x over previous
#include <cuda_runtime.h>
#include <cuda_bf16.h>
#include <cstdint>

#define N_Q   16384
#define DIMS  64
#define K_CB  8192
#define MT    128            // queries per CTA
#define NT    128            // codewords per tile
#define NTILES (K_CB / NT)   // 64
#define THREADS 256

// padded bf16 row: 64 elems + 8 pad = 72 elems = 144 bytes
#define ROWB 144
#define TERM_BYTES (128 * ROWB)      // 18432 per term (128 rows)

// shared memory layout (bytes)
#define SM_A     0                        // 2 terms  (36864)
#define SM_B     36864                    // 2 stages x 2 terms (73728)
#define SM_CSQ   110592                   // 2 stages x 512
#define SM_CAND  111616                   // 128 q x 16 slots x 2 ints (16384)
#define SM_BESTK 128000                   // 128 ints
#define SMEM_TOTAL 128512

__device__ __nv_bfloat16 g_enc_hi[N_Q * DIMS];
__device__ __nv_bfloat16 g_enc_lo[N_Q * DIMS];
__device__ __nv_bfloat16 g_cb_hi[K_CB * DIMS];
__device__ __nv_bfloat16 g_cb_lo[K_CB * DIMS];
__device__ __align__(16) float g_csq[K_CB];

// ---------------- helpers ----------------
__device__ __forceinline__ uint32_t smem_u32(const void* p) {
    uint32_t a;
    asm("{ .reg .u64 t; cvta.to.shared.u64 t, %1; cvt.u32.u64 %0, t; }" : "=r"(a) : "l"(p));
    return a;
}
#define CP16(d, s)  asm volatile("cp.async.cg.shared.global [%0], [%1], 16;" :: "r"(d), "l"(s))
#define CP_COMMIT() asm volatile("cp.async.commit_group;" ::: "memory")

__device__ __forceinline__ void ldsm_x4(uint32_t* r, uint32_t addr) {
    asm volatile("ldmatrix.sync.aligned.m8n8.x4.shared.b16 {%0,%1,%2,%3}, [%4];"
                 : "=r"(r[0]), "=r"(r[1]), "=r"(r[2]), "=r"(r[3]) : "r"(addr));
}
__device__ __forceinline__ void mma16816(float* c, const uint32_t* a, const uint32_t* b) {
    asm volatile("mma.sync.aligned.m16n8k16.row.col.f32.bf16.bf16.f32 "
                 "{%0,%1,%2,%3}, {%4,%5,%6,%7}, {%8,%9}, {%0,%1,%2,%3};"
                 : "+f"(c[0]), "+f"(c[1]), "+f"(c[2]), "+f"(c[3])
                 : "r"(a[0]), "r"(a[1]), "r"(a[2]), "r"(a[3]), "r"(b[0]), "r"(b[1]));
}

// ---------------- preprocessing ----------------
__global__ void prep_kernel(const float* __restrict__ enc, const float* __restrict__ cb) {
    int idx = blockIdx.x * blockDim.x + threadIdx.x;     // one float4
    const int n4e = N_Q * DIMS / 4;
    const float4* src;
    __nv_bfloat162 *ph, *pl;
    int j;
    if (idx < n4e) { src = (const float4*)enc; j = idx;
        ph = (__nv_bfloat162*)g_enc_hi; pl = (__nv_bfloat162*)g_enc_lo; }
    else { src = (const float4*)cb; j = idx - n4e;
        ph = (__nv_bfloat162*)g_cb_hi;  pl = (__nv_bfloat162*)g_cb_lo; }
    float4 v = src[j];
    __nv_bfloat16 hx = __float2bfloat16(v.x), hy = __float2bfloat16(v.y);
    __nv_bfloat16 hz = __float2bfloat16(v.z), hw = __float2bfloat16(v.w);
    __nv_bfloat16 lx = __float2bfloat16(v.x - __bfloat162float(hx));
    __nv_bfloat16 ly = __float2bfloat16(v.y - __bfloat162float(hy));
    __nv_bfloat16 lz = __float2bfloat16(v.z - __bfloat162float(hz));
    __nv_bfloat16 lw = __float2bfloat16(v.w - __bfloat162float(hw));
    __nv_bfloat162 a; a.x = hx; a.y = hy;
    __nv_bfloat162 b; b.x = hz; b.y = hw;
    __nv_bfloat162 c; c.x = lx; c.y = ly;
    __nv_bfloat162 d; d.x = lz; d.y = lw;
    ph[j * 2] = a; ph[j * 2 + 1] = b;
    pl[j * 2] = c; pl[j * 2 + 1] = d;
}

__global__ void csq_kernel(const float* __restrict__ cb) {
    int row  = blockIdx.x * 8 + (threadIdx.x >> 5);
    int lane = threadIdx.x & 31;
    float v0 = cb[row * DIMS + lane];
    float v1 = cb[row * DIMS + 32 + lane];
    float s  = v0 * v0 + v1 * v1;
    #pragma unroll
    for (int off = 16; off; off >>= 1) s += __shfl_xor_sync(0xffffffffu, s, off);
    if (lane == 0) g_csq[row] = s;
}

// ---------------- main kernel ----------------
__device__ __forceinline__ void load_B_tile(uint32_t smem_base, int tile, int stage, int tid) {
    const int kb = tile * NT;
    // 2 terms x 128 rows x 8 chunks (16B) = 2048 chunks, 8 per thread
    #pragma unroll
    for (int i = 0; i < 8; ++i) {
        int c = tid + i * THREADS;
        int v = c >> 10;                  // term: 0=hi, 1=lo
        int r = (c >> 3) & 127;           // codeword row within tile
        int q = c & 7;                    // 16B chunk
        const char* src = (const char*)(v ? g_cb_lo : g_cb_hi) + (size_t)(kb + r) * 128 + q * 16;
        uint32_t dst = smem_base + SM_B + stage * (2 * TERM_BYTES) + v * TERM_BYTES
                     + r * ROWB + q * 16;
        CP16(dst, src);
    }
    if (tid < 32) {
        uint32_t dst = smem_base + SM_CSQ + stage * 512 + tid * 16;
        CP16(dst, (const char*)g_csq + (size_t)kb * 4 + tid * 16);
    }
}

__global__ __launch_bounds__(THREADS, 1)
void vq_main(const float* __restrict__ enc, const float* __restrict__ cb,
             float* __restrict__ out)
{
    extern __shared__ char smem[];
    const uint32_t smem_base = smem_u32(smem);
    const int tid    = threadIdx.x;
    const int wid    = tid >> 5;
    const int lane   = tid & 31;
    const int warp_m = wid & 1;           // 2 warps over M (64 rows each)
    const int warp_n = wid >> 1;          // 4 warps over N (32 cols each)
    const int m0     = blockIdx.x * MT;

    // ---- stage A (both split terms), padded rows ----
    #pragma unroll
    for (int i = 0; i < 8; ++i) {
        int c = tid + i * THREADS;
        int v = c >> 10;
        int r = (c >> 3) & 127;
        int q = c & 7;
        const uint4* src = (const uint4*)((v ? g_enc_lo : g_enc_hi) + (size_t)(m0 + r) * DIMS) + q;
        *(uint4*)(smem + SM_A + v * TERM_BYTES + r * ROWB + q * 16) = *src;
    }

    // ---- pipeline prologue ----
    load_B_tile(smem_base, 0, 0, tid); CP_COMMIT();

    // ldmatrix base addresses
    const uint32_t a_base = smem_base + SM_A
        + (warp_m * 64 + (lane & 15)) * ROWB + ((lane >> 4) & 1) * 16;
    const uint32_t b_base = smem_base + SM_B
        + (warp_n * 32 + (lane >> 4) * 8 + (lane & 7)) * ROWB + ((lane >> 3) & 1) * 16;

    float bm1[8], bm2[8];
    int   bi1[8], bi2[8];
    #pragma unroll
    for (int r = 0; r < 8; ++r) { bm1[r] = 3.4e38f; bm2[r] = 3.4e38f; bi1[r] = 0; bi2[r] = 0; }

    float acc[4][4][4];

    for (int t = 0; t < NTILES; ++t) {
        const int stage = t & 1;
        if (t + 1 < NTILES) {
            load_B_tile(smem_base, t + 1, stage ^ 1, tid); CP_COMMIT();
            asm volatile("cp.async.wait_group 1;" ::: "memory");
        } else {
            asm volatile("cp.async.wait_group 0;" ::: "memory");
        }
        __syncthreads();

        #pragma unroll
        for (int i = 0; i < 4; ++i)
            #pragma unroll
            for (int j = 0; j < 4; ++j)
                #pragma unroll
                for (int r = 0; r < 4; ++r) acc[i][j][r] = 0.f;

        // 3 split terms: (Ah,Bh), (Ah,Bl), (Al,Bh)
        #pragma unroll
        for (int pass = 0; pass < 3; ++pass) {
            const uint32_t aoff = (pass == 2) ? TERM_BYTES : 0;
            const uint32_t boff = stage * (2 * TERM_BYTES) + ((pass == 1) ? TERM_BYTES : 0);
            #pragma unroll
            for (int ks = 0; ks < 4; ++ks) {
                uint32_t af[4][4], bf[4][2];
                #pragma unroll
                for (int i = 0; i < 4; ++i)
                    ldsm_x4(af[i], a_base + aoff + i * 16 * ROWB + ks * 32);
                {
                    uint32_t r0[4], r1[4];
                    ldsm_x4(r0, b_base + boff + ks * 32);                  // j=0,1
                    ldsm_x4(r1, b_base + boff + 16 * ROWB + ks * 32);      // j=2,3
                    bf[0][0] = r0[0]; bf[0][1] = r0[1];
                    bf[1][0] = r0[2]; bf[1][1] = r0[3];
                    bf[2][0] = r1[0]; bf[2][1] = r1[1];
                    bf[3][0] = r1[2]; bf[3][1] = r1[3];
                }
                #pragma unroll
                for (int i = 0; i < 4; ++i)
                    #pragma unroll
                    for (int j = 0; j < 4; ++j)
                        mma16816(acc[i][j], af[i], bf[j]);
            }
        }

        // ---- fused argmin epilogue (top-2 per owned query row) ----
        const int kb = t * NT;
        #pragma unroll
        for (int j = 0; j < 4; ++j) {
            float2 cs = *(const float2*)(smem + SM_CSQ + stage * 512
                        + (warp_n * 32 + j * 8 + (lane & 3) * 2) * 4);
            const int k0 = kb + warp_n * 32 + j * 8 + (lane & 3) * 2;
            #pragma unroll
            for (int i = 0; i < 4; ++i) {
                #pragma unroll
                for (int h = 0; h < 2; ++h) {
                    const int ri = i * 2 + h;
                    float m0v = fmaf(-2.f, acc[i][j][h * 2 + 0], cs.x);
                    if (m0v < bm2[ri]) {
                        if (m0v < bm1[ri]) { bm2[ri] = bm1[ri]; bi2[ri] = bi1[ri];
                                             bm1[ri] = m0v;     bi1[ri] = k0; }
                        else               { bm2[ri] = m0v;     bi2[ri] = k0; }
                    }
                    float m1v = fmaf(-2.f, acc[i][j][h * 2 + 1], cs.y);
                    if (m1v < bm2[ri]) {
                        if (m1v < bm1[ri]) { bm2[ri] = bm1[ri]; bi2[ri] = bi1[ri];
                                             bm1[ri] = m1v;     bi1[ri] = k0 + 1; }
                        else               { bm2[ri] = m1v;     bi2[ri] = k0 + 1; }
                    }
                }
            }
        }
        __syncthreads();   // all reads of this stage done before it is overwritten
    }

    // ---- candidate dump: 16 slots x 2 per query ----
    {
        int* cand = (int*)(smem + SM_CAND);
        const int slot = warp_n * 4 + (lane & 3);
        #pragma unroll
        for (int i = 0; i < 4; ++i)
            #pragma unroll
            for (int h = 0; h < 2; ++h) {
                const int ri = i * 2 + h;
                const int q  = warp_m * 64 + i * 16 + h * 8 + (lane >> 2);
                cand[(q * 16 + slot) * 2 + 0] = bi1[ri];
                cand[(q * 16 + slot) * 2 + 1] = bi2[ri];
            }
    }
    __syncthreads();

    // ---- exact fp32 rescore: one warp per query, one candidate per lane ----
    {
        const int* cand = (const int*)(smem + SM_CAND);
        int* bestk = (int*)(smem + SM_BESTK);
        for (int it = 0; it < 16; ++it) {
            const int q = wid * 16 + it;
            const int k = cand[q * 32 + lane];
            const float4* er = (const float4*)(enc + (size_t)(m0 + q) * DIMS);
            const float4* cr = (const float4*)(cb + (size_t)k * DIMS);
            float s = 0.f;
            #pragma unroll
            for (int u = 0; u < 16; ++u) {
                float4 a = er[u], b = cr[u];
                s = fmaf(a.x, b.x, s); s = fmaf(a.y, b.y, s);
                s = fmaf(a.z, b.z, s); s = fmaf(a.w, b.w, s);
            }
            float m = fmaf(-2.f, s, g_csq[k]);
            int   bk = k;
            #pragma unroll
            for (int off = 16; off; off >>= 1) {
                float om = __shfl_xor_sync(0xffffffffu, m, off);
                int   ok = __shfl_xor_sync(0xffffffffu, bk, off);
                if (om < m || (om == m && ok < bk)) { m = om; bk = ok; }
            }
            if (lane == 0) bestk[q] = bk;
        }
    }
    __syncthreads();

    // ---- gather output rows ----
    {
        const int* bestk = (const int*)(smem + SM_BESTK);
        const float4* cb4 = (const float4*)cb;
        float4* out4 = (float4*)out;
        #pragma unroll
        for (int i = 0; i < 8; ++i) {
            int lin = tid + i * THREADS;            // 0..2047
            int q = lin >> 4;
            int quad = lin & 15;
            out4[(size_t)(m0 + q) * 16 + quad] = cb4[(size_t)bestk[q] * 16 + quad];
        }
    }
}

extern "C" void kernel_launch(void* const* d_in, const int* in_sizes, int n_in,
                              void* d_out, int out_size) {
    const float* enc = (const float*)d_in[0];
    const float* cb  = (const float*)d_in[1];
    if (n_in >= 2 && in_sizes[0] == K_CB * DIMS && in_sizes[1] == N_Q * DIMS) {
        enc = (const float*)d_in[1];
        cb  = (const float*)d_in[0];
    }
    float* out = (float*)d_out;

    cudaFuncSetAttribute(vq_main, cudaFuncAttributeMaxDynamicSharedMemorySize, SMEM_TOTAL);

    prep_kernel<<<(N_Q * DIMS + K_CB * DIMS) / 4 / 256, 256>>>(enc, cb);
    csq_kernel<<<K_CB / 8, 256>>>(cb);
    vq_main<<<N_Q / MT, THREADS, SMEM_TOTAL>>>(enc, cb, out);
}

// round 5
// speedup vs baseline: 2.6638x; 1.0261x over previous
#include <cuda_runtime.h>
#include <cuda_bf16.h>
#include <cstdint>

#define N_Q   16384
#define DIMS  64
#define K_CB  8192
#define MT    128            // queries per CTA
#define NT    128            // codewords per tile
#define NTILES (K_CB / NT)   // 64
#define THREADS 256

// padded bf16 row: 64 elems + 8 pad = 72 elems = 144 bytes
#define ROWB 144
#define TERM_BYTES (128 * ROWB)      // 18432 per term (128 rows)
#define STAGE (2 * TERM_BYTES + 512) // hi + lo + csq = 37376 (128B aligned)
#define NSTAGE 4

// shared memory layout (bytes)
#define SM_B     0                       // 4 stages x 37376 = 149504
#define SM_A     149504                  // hi 18432 + lo 18432
#define SM_A_LO  (SM_A + TERM_BYTES)
#define SM_CAND  186368                  // 128 q x 16 slots x 2 ints (16384)
#define SM_BESTK 202752                  // 128 ints
#define SMEM_TOTAL 203264

__device__ __nv_bfloat16 g_enc_hi[N_Q * DIMS];
__device__ __nv_bfloat16 g_enc_lo[N_Q * DIMS];
__device__ __nv_bfloat16 g_cb_hi[K_CB * DIMS];
__device__ __nv_bfloat16 g_cb_lo[K_CB * DIMS];
__device__ __align__(16) float g_csq[K_CB];

// ---------------- helpers ----------------
__device__ __forceinline__ uint32_t smem_u32(const void* p) {
    uint32_t a;
    asm("{ .reg .u64 t; cvta.to.shared.u64 t, %1; cvt.u32.u64 %0, t; }" : "=r"(a) : "l"(p));
    return a;
}
#define CP16(d, s)  asm volatile("cp.async.cg.shared.global [%0], [%1], 16;" :: "r"(d), "l"(s))
#define CP_COMMIT() asm volatile("cp.async.commit_group;" ::: "memory")
#define CP_WAIT2()  asm volatile("cp.async.wait_group 2;" ::: "memory")

__device__ __forceinline__ void ldsm_x4(uint32_t* r, uint32_t addr) {
    asm volatile("ldmatrix.sync.aligned.m8n8.x4.shared.b16 {%0,%1,%2,%3}, [%4];"
                 : "=r"(r[0]), "=r"(r[1]), "=r"(r[2]), "=r"(r[3]) : "r"(addr));
}
__device__ __forceinline__ void ldsm_x2(uint32_t* r, uint32_t addr) {
    asm volatile("ldmatrix.sync.aligned.m8n8.x2.shared.b16 {%0,%1}, [%2];"
                 : "=r"(r[0]), "=r"(r[1]) : "r"(addr));
}
__device__ __forceinline__ void mma16816(float* c, const uint32_t* a, const uint32_t* b) {
    asm volatile("mma.sync.aligned.m16n8k16.row.col.f32.bf16.bf16.f32 "
                 "{%0,%1,%2,%3}, {%4,%5,%6,%7}, {%8,%9}, {%0,%1,%2,%3};"
                 : "+f"(c[0]), "+f"(c[1]), "+f"(c[2]), "+f"(c[3])
                 : "r"(a[0]), "r"(a[1]), "r"(a[2]), "r"(a[3]), "r"(b[0]), "r"(b[1]));
}

// ---------------- preprocessing ----------------
__global__ void prep_kernel(const float* __restrict__ enc, const float* __restrict__ cb) {
    int idx = blockIdx.x * blockDim.x + threadIdx.x;     // one float4
    const int n4e = N_Q * DIMS / 4;
    const float4* src;
    __nv_bfloat162 *ph, *pl;
    int j;
    if (idx < n4e) { src = (const float4*)enc; j = idx;
        ph = (__nv_bfloat162*)g_enc_hi; pl = (__nv_bfloat162*)g_enc_lo; }
    else { src = (const float4*)cb; j = idx - n4e;
        ph = (__nv_bfloat162*)g_cb_hi;  pl = (__nv_bfloat162*)g_cb_lo; }
    float4 v = src[j];
    __nv_bfloat16 hx = __float2bfloat16(v.x), hy = __float2bfloat16(v.y);
    __nv_bfloat16 hz = __float2bfloat16(v.z), hw = __float2bfloat16(v.w);
    __nv_bfloat16 lx = __float2bfloat16(v.x - __bfloat162float(hx));
    __nv_bfloat16 ly = __float2bfloat16(v.y - __bfloat162float(hy));
    __nv_bfloat16 lz = __float2bfloat16(v.z - __bfloat162float(hz));
    __nv_bfloat16 lw = __float2bfloat16(v.w - __bfloat162float(hw));
    __nv_bfloat162 a; a.x = hx; a.y = hy;
    __nv_bfloat162 b; b.x = hz; b.y = hw;
    __nv_bfloat162 c; c.x = lx; c.y = ly;
    __nv_bfloat162 d; d.x = lz; d.y = lw;
    ph[j * 2] = a; ph[j * 2 + 1] = b;
    pl[j * 2] = c; pl[j * 2 + 1] = d;
}

__global__ void csq_kernel(const float* __restrict__ cb) {
    int row  = blockIdx.x * 8 + (threadIdx.x >> 5);
    int lane = threadIdx.x & 31;
    float v0 = cb[row * DIMS + lane];
    float v1 = cb[row * DIMS + 32 + lane];
    float s  = v0 * v0 + v1 * v1;
    #pragma unroll
    for (int off = 16; off; off >>= 1) s += __shfl_xor_sync(0xffffffffu, s, off);
    if (lane == 0) g_csq[row] = s;
}

// ---------------- B tile loader ----------------
__device__ __forceinline__ void load_B_tile(uint32_t smem_base, int tile, int stage, int tid) {
    const int kb = tile * NT;
    #pragma unroll
    for (int i = 0; i < 8; ++i) {
        int c = tid + i * THREADS;
        int v = c >> 10;                  // term: 0=hi, 1=lo
        int r = (c >> 3) & 127;           // codeword row within tile
        int q = c & 7;                    // 16B chunk
        const char* src = (const char*)(v ? g_cb_lo : g_cb_hi) + (size_t)(kb + r) * 128 + q * 16;
        uint32_t dst = smem_base + SM_B + stage * STAGE + v * TERM_BYTES + r * ROWB + q * 16;
        CP16(dst, src);
    }
    if (tid < 32) {
        uint32_t dst = smem_base + SM_B + stage * STAGE + 2 * TERM_BYTES + tid * 16;
        CP16(dst, (const char*)g_csq + (size_t)kb * 4 + tid * 16);
    }
}

// ---------------- main kernel ----------------
__global__ __launch_bounds__(THREADS, 1)
void vq_main(const float* __restrict__ enc, const float* __restrict__ cb,
             float* __restrict__ out)
{
    extern __shared__ char smem[];
    const uint32_t smem_base = smem_u32(smem);
    const int tid    = threadIdx.x;
    const int wid    = tid >> 5;
    const int lane   = tid & 31;
    const int warp_m = wid & 1;           // 2 warps over M (64 rows each)
    const int warp_n = wid >> 1;          // 4 warps over N (32 cols each)
    const int m0     = blockIdx.x * MT;

    // ---- start B pipeline immediately (stages 0..2) ----
    load_B_tile(smem_base, 0, 0, tid); CP_COMMIT();
    load_B_tile(smem_base, 1, 1, tid); CP_COMMIT();
    load_B_tile(smem_base, 2, 2, tid); CP_COMMIT();

    // ---- stage A (both split terms), padded rows ----
    #pragma unroll
    for (int i = 0; i < 8; ++i) {
        int c = tid + i * THREADS;
        int v = c >> 10;
        int r = (c >> 3) & 127;
        int q = c & 7;
        const uint4* src = (const uint4*)((v ? g_enc_lo : g_enc_hi) + (size_t)(m0 + r) * DIMS) + q;
        *(uint4*)(smem + (v ? SM_A_LO : SM_A) + r * ROWB + q * 16) = *src;
    }
    __syncthreads();

    // ldmatrix base addresses
    const uint32_t a_base_hi = smem_base + SM_A
        + (warp_m * 64 + (lane & 15)) * ROWB + ((lane >> 4) & 1) * 16;
    const uint32_t a_base_lo = a_base_hi + TERM_BYTES;
    const uint32_t b_base = smem_base + SM_B
        + (warp_n * 32 + (lane >> 4) * 8 + (lane & 7)) * ROWB + ((lane >> 3) & 1) * 16;

    // ---- hoist A-hi fragments: tile-invariant ----
    uint32_t afh[4][4][4];                // [ks][i][frag]
    #pragma unroll
    for (int ks = 0; ks < 4; ++ks)
        #pragma unroll
        for (int i = 0; i < 4; ++i)
            ldsm_x4(afh[ks][i], a_base_hi + i * 16 * ROWB + ks * 32);

    float bm1[8], bm2[8];
    int   bi1[8], bi2[8];
    #pragma unroll
    for (int r = 0; r < 8; ++r) { bm1[r] = 3.4e38f; bm2[r] = 3.4e38f; bi1[r] = 0; bi2[r] = 0; }

    float acc[4][4][4];

    for (int t = 0; t < NTILES; ++t) {
        const int stage = t & 3;
        CP_WAIT2();                       // oldest pending (tile t) complete
        __syncthreads();                  // visible to all warps; stage (t-1)&3 fully consumed
        if (t + 3 < NTILES) load_B_tile(smem_base, t + 3, (t + 3) & 3, tid);
        CP_COMMIT();                      // commit (possibly empty) to keep group counts uniform

        #pragma unroll
        for (int i = 0; i < 4; ++i)
            #pragma unroll
            for (int j = 0; j < 4; ++j)
                #pragma unroll
                for (int r = 0; r < 4; ++r) acc[i][j][r] = 0.f;

        const uint32_t bs = b_base + stage * STAGE;
        #pragma unroll
        for (int ks = 0; ks < 4; ++ks) {
            // B-hi fragments (shared by Ah and Al passes)
            uint32_t bh[4][2];
            {
                uint32_t r0[4], r1[4];
                ldsm_x4(r0, bs + ks * 32);
                ldsm_x4(r1, bs + 16 * ROWB + ks * 32);
                bh[0][0] = r0[0]; bh[0][1] = r0[1];
                bh[1][0] = r0[2]; bh[1][1] = r0[3];
                bh[2][0] = r1[0]; bh[2][1] = r1[1];
                bh[3][0] = r1[2]; bh[3][1] = r1[3];
            }
            // A-lo fragments for this ks
            uint32_t al[4][4];
            #pragma unroll
            for (int i = 0; i < 4; ++i)
                ldsm_x4(al[i], a_base_lo + i * 16 * ROWB + ks * 32);
            // Ah*Bh
            #pragma unroll
            for (int i = 0; i < 4; ++i)
                #pragma unroll
                for (int j = 0; j < 4; ++j) mma16816(acc[i][j], afh[ks][i], bh[j]);
            // Al*Bh
            #pragma unroll
            for (int i = 0; i < 4; ++i)
                #pragma unroll
                for (int j = 0; j < 4; ++j) mma16816(acc[i][j], al[i], bh[j]);
            // B-lo fragments, Ah*Bl
            uint32_t bl[4][2];
            {
                uint32_t r0[4], r1[4];
                ldsm_x4(r0, bs + TERM_BYTES + ks * 32);
                ldsm_x4(r1, bs + TERM_BYTES + 16 * ROWB + ks * 32);
                bl[0][0] = r0[0]; bl[0][1] = r0[1];
                bl[1][0] = r0[2]; bl[1][1] = r0[3];
                bl[2][0] = r1[0]; bl[2][1] = r1[1];
                bl[3][0] = r1[2]; bl[3][1] = r1[3];
            }
            #pragma unroll
            for (int i = 0; i < 4; ++i)
                #pragma unroll
                for (int j = 0; j < 4; ++j) mma16816(acc[i][j], afh[ks][i], bl[j]);
        }

        // ---- fused argmin epilogue (top-2 per owned query row) ----
        const int kb = t * NT;
        #pragma unroll
        for (int j = 0; j < 4; ++j) {
            float2 cs = *(const float2*)(smem + SM_B + stage * STAGE + 2 * TERM_BYTES
                        + (warp_n * 32 + j * 8 + (lane & 3) * 2) * 4);
            const int k0 = kb + warp_n * 32 + j * 8 + (lane & 3) * 2;
            #pragma unroll
            for (int i = 0; i < 4; ++i) {
                #pragma unroll
                for (int h = 0; h < 2; ++h) {
                    const int ri = i * 2 + h;
                    float m0v = fmaf(-2.f, acc[i][j][h * 2 + 0], cs.x);
                    if (m0v < bm2[ri]) {
                        if (m0v < bm1[ri]) { bm2[ri] = bm1[ri]; bi2[ri] = bi1[ri];
                                             bm1[ri] = m0v;     bi1[ri] = k0; }
                        else               { bm2[ri] = m0v;     bi2[ri] = k0; }
                    }
                    float m1v = fmaf(-2.f, acc[i][j][h * 2 + 1], cs.y);
                    if (m1v < bm2[ri]) {
                        if (m1v < bm1[ri]) { bm2[ri] = bm1[ri]; bi2[ri] = bi1[ri];
                                             bm1[ri] = m1v;     bi1[ri] = k0 + 1; }
                        else               { bm2[ri] = m1v;     bi2[ri] = k0 + 1; }
                    }
                }
            }
        }
        // no trailing sync: next iteration's leading sync protects stage reuse
    }

    // ---- candidate dump: 16 slots x 2 per query ----
    __syncthreads();
    {
        int* cand = (int*)(smem + SM_CAND);
        const int slot = warp_n * 4 + (lane & 3);
        #pragma unroll
        for (int i = 0; i < 4; ++i)
            #pragma unroll
            for (int h = 0; h < 2; ++h) {
                const int ri = i * 2 + h;
                const int q  = warp_m * 64 + i * 16 + h * 8 + (lane >> 2);
                cand[(q * 16 + slot) * 2 + 0] = bi1[ri];
                cand[(q * 16 + slot) * 2 + 1] = bi2[ri];
            }
    }
    __syncthreads();

    // ---- exact fp32 rescore: one warp per query, one candidate per lane ----
    {
        const int* cand = (const int*)(smem + SM_CAND);
        int* bestk = (int*)(smem + SM_BESTK);
        for (int it = 0; it < 16; ++it) {
            const int q = wid * 16 + it;
            const int k = cand[q * 32 + lane];
            const float4* er = (const float4*)(enc + (size_t)(m0 + q) * DIMS);
            const float4* cr = (const float4*)(cb + (size_t)k * DIMS);
            float s = 0.f;
            #pragma unroll
            for (int u = 0; u < 16; ++u) {
                float4 a = er[u], b = cr[u];
                s = fmaf(a.x, b.x, s); s = fmaf(a.y, b.y, s);
                s = fmaf(a.z, b.z, s); s = fmaf(a.w, b.w, s);
            }
            float m = fmaf(-2.f, s, g_csq[k]);
            int   bk = k;
            #pragma unroll
            for (int off = 16; off; off >>= 1) {
                float om = __shfl_xor_sync(0xffffffffu, m, off);
                int   ok = __shfl_xor_sync(0xffffffffu, bk, off);
                if (om < m || (om == m && ok < bk)) { m = om; bk = ok; }
            }
            if (lane == 0) bestk[q] = bk;
        }
    }
    __syncthreads();

    // ---- gather output rows ----
    {
        const int* bestk = (const int*)(smem + SM_BESTK);
        const float4* cb4 = (const float4*)cb;
        float4* out4 = (float4*)out;
        #pragma unroll
        for (int i = 0; i < 8; ++i) {
            int lin = tid + i * THREADS;            // 0..2047
            int q = lin >> 4;
            int quad = lin & 15;
            out4[(size_t)(m0 + q) * 16 + quad] = cb4[(size_t)bestk[q] * 16 + quad];
        }
    }
}

extern "C" void kernel_launch(void* const* d_in, const int* in_sizes, int n_in,
                              void* d_out, int out_size) {
    const float* enc = (const float*)d_in[0];
    const float* cb  = (const float*)d_in[1];
    if (n_in >= 2 && in_sizes[0] == K_CB * DIMS && in_sizes[1] == N_Q * DIMS) {
        enc = (const float*)d_in[1];
        cb  = (const float*)d_in[0];
    }
    float* out = (float*)d_out;

    cudaFuncSetAttribute(vq_main, cudaFuncAttributeMaxDynamicSharedMemorySize, SMEM_TOTAL);

    prep_kernel<<<(N_Q * DIMS + K_CB * DIMS) / 4 / 256, 256>>>(enc, cb);
    csq_kernel<<<K_CB / 8, 256>>>(cb);
    vq_main<<<N_Q / MT, THREADS, SMEM_TOTAL>>>(enc, cb, out);
}

// round 6
// speedup vs baseline: 2.8164x; 1.0573x over previous
#include <cuda_runtime.h>
#include <cuda_bf16.h>
#include <cstdint>

#define N_Q   16384
#define DIMS  64
#define K_CB  8192
#define MT    128            // queries per CTA
#define NT    128            // codewords per tile
#define NTILES (K_CB / NT)   // 64
#define THREADS 256

// padded bf16 row: 64 elems + 8 pad = 72 elems = 144 bytes
#define ROWB 144
#define TERM_BYTES (128 * ROWB)      // 18432 per tile (128 rows)
#define STAGE (TERM_BYTES + 512)     // tile + csq = 18944
#define TAU 2.0f

// shared memory layout (bytes)
#define SM_B     0                       // 4 stages x 18944 = 75776
#define SM_A     75776                   // 18432
#define SM_CAND  94208                   // 128 q x 48 slots x 8B = 49152
#define SM_BESTK 143360                  // 128 ints
#define SMEM_TOTAL 143872

__device__ __nv_bfloat16 g_enc_bf[N_Q * DIMS];
__device__ __nv_bfloat16 g_cb_bf[K_CB * DIMS];
__device__ __align__(16) float g_csq[K_CB];

// ---------------- helpers ----------------
__device__ __forceinline__ uint32_t smem_u32(const void* p) {
    uint32_t a;
    asm("{ .reg .u64 t; cvta.to.shared.u64 t, %1; cvt.u32.u64 %0, t; }" : "=r"(a) : "l"(p));
    return a;
}
#define CP16(d, s)  asm volatile("cp.async.cg.shared.global [%0], [%1], 16;" :: "r"(d), "l"(s))
#define CP_COMMIT() asm volatile("cp.async.commit_group;" ::: "memory")
#define CP_WAIT2()  asm volatile("cp.async.wait_group 2;" ::: "memory")

__device__ __forceinline__ void ldsm_x4(uint32_t* r, uint32_t addr) {
    asm volatile("ldmatrix.sync.aligned.m8n8.x4.shared.b16 {%0,%1,%2,%3}, [%4];"
                 : "=r"(r[0]), "=r"(r[1]), "=r"(r[2]), "=r"(r[3]) : "r"(addr));
}
__device__ __forceinline__ void mma16816(float* c, const uint32_t* a, const uint32_t* b) {
    asm volatile("mma.sync.aligned.m16n8k16.row.col.f32.bf16.bf16.f32 "
                 "{%0,%1,%2,%3}, {%4,%5,%6,%7}, {%8,%9}, {%0,%1,%2,%3};"
                 : "+f"(c[0]), "+f"(c[1]), "+f"(c[2]), "+f"(c[3])
                 : "r"(a[0]), "r"(a[1]), "r"(a[2]), "r"(a[3]), "r"(b[0]), "r"(b[1]));
}

// ---------------- preprocessing ----------------
__global__ void prep_kernel(const float* __restrict__ enc, const float* __restrict__ cb) {
    int idx = blockIdx.x * blockDim.x + threadIdx.x;     // one float4
    const int n4e = N_Q * DIMS / 4;
    const float4* src;
    __nv_bfloat162* ph;
    int j;
    if (idx < n4e) { src = (const float4*)enc; j = idx; ph = (__nv_bfloat162*)g_enc_bf; }
    else           { src = (const float4*)cb;  j = idx - n4e; ph = (__nv_bfloat162*)g_cb_bf; }
    float4 v = src[j];
    __nv_bfloat162 a; a.x = __float2bfloat16(v.x); a.y = __float2bfloat16(v.y);
    __nv_bfloat162 b; b.x = __float2bfloat16(v.z); b.y = __float2bfloat16(v.w);
    ph[j * 2] = a; ph[j * 2 + 1] = b;
}

__global__ void csq_kernel(const float* __restrict__ cb) {
    int row  = blockIdx.x * 8 + (threadIdx.x >> 5);
    int lane = threadIdx.x & 31;
    float v0 = cb[row * DIMS + lane];
    float v1 = cb[row * DIMS + 32 + lane];
    float s  = v0 * v0 + v1 * v1;
    #pragma unroll
    for (int off = 16; off; off >>= 1) s += __shfl_xor_sync(0xffffffffu, s, off);
    if (lane == 0) g_csq[row] = s;
}

// ---------------- B tile loader ----------------
__device__ __forceinline__ void load_B_tile(uint32_t smem_base, int tile, int stage, int tid) {
    const int kb = tile * NT;
    #pragma unroll
    for (int i = 0; i < 4; ++i) {
        int c = tid + i * THREADS;        // 0..1023
        int r = c >> 3;                   // codeword row within tile
        int q = c & 7;                    // 16B chunk
        const char* src = (const char*)g_cb_bf + (size_t)(kb + r) * 128 + q * 16;
        uint32_t dst = smem_base + SM_B + stage * STAGE + r * ROWB + q * 16;
        CP16(dst, src);
    }
    if (tid < 32) {
        uint32_t dst = smem_base + SM_B + stage * STAGE + TERM_BYTES + tid * 16;
        CP16(dst, (const char*)g_csq + (size_t)kb * 4 + tid * 16);
    }
}

// ---------------- main kernel ----------------
__global__ __launch_bounds__(THREADS, 1)
void vq_main(const float* __restrict__ enc, const float* __restrict__ cb,
             float* __restrict__ out)
{
    extern __shared__ char smem[];
    const uint32_t smem_base = smem_u32(smem);
    const int tid    = threadIdx.x;
    const int wid    = tid >> 5;
    const int lane   = tid & 31;
    const int warp_m = wid & 1;           // 2 warps over M (64 rows each)
    const int warp_n = wid >> 1;          // 4 warps over N (32 cols each)
    const int m0     = blockIdx.x * MT;

    // ---- start B pipeline immediately (stages 0..2) ----
    load_B_tile(smem_base, 0, 0, tid); CP_COMMIT();
    load_B_tile(smem_base, 1, 1, tid); CP_COMMIT();
    load_B_tile(smem_base, 2, 2, tid); CP_COMMIT();

    // ---- stage A (bf16), padded rows ----
    #pragma unroll
    for (int i = 0; i < 4; ++i) {
        int c = tid + i * THREADS;        // 0..1023
        int r = c >> 3;
        int q = c & 7;
        const uint4* src = (const uint4*)(g_enc_bf + (size_t)(m0 + r) * DIMS) + q;
        *(uint4*)(smem + SM_A + r * ROWB + q * 16) = *src;
    }
    __syncthreads();

    // ldmatrix base addresses
    const uint32_t a_base = smem_base + SM_A
        + (warp_m * 64 + (lane & 15)) * ROWB + ((lane >> 4) & 1) * 16;
    const uint32_t b_base = smem_base + SM_B
        + (warp_n * 32 + (lane >> 4) * 8 + (lane & 7)) * ROWB + ((lane >> 3) & 1) * 16;

    // ---- hoist A fragments (tile-invariant) ----
    uint32_t af[4][4][4];                 // [ks][i][frag]
    #pragma unroll
    for (int ks = 0; ks < 4; ++ks)
        #pragma unroll
        for (int i = 0; i < 4; ++i)
            ldsm_x4(af[ks][i], a_base + i * 16 * ROWB + ks * 32);

    // top-3 per owned query row (8 rows/thread)
    float bm1[8], bm2[8], bm3[8];
    int   bi1[8], bi2[8], bi3[8];
    #pragma unroll
    for (int r = 0; r < 8; ++r) {
        bm1[r] = 3.4e38f; bm2[r] = 3.4e38f; bm3[r] = 3.4e38f;
        bi1[r] = 0; bi2[r] = 0; bi3[r] = 0;
    }

    float acc[4][4][4];

    for (int t = 0; t < NTILES; ++t) {
        const int stage = t & 3;
        CP_WAIT2();                       // tile t resident
        __syncthreads();                  // stage (t+3)&3 fully consumed by all warps
        if (t + 3 < NTILES) load_B_tile(smem_base, t + 3, (t + 3) & 3, tid);
        CP_COMMIT();

        #pragma unroll
        for (int i = 0; i < 4; ++i)
            #pragma unroll
            for (int j = 0; j < 4; ++j)
                #pragma unroll
                for (int r = 0; r < 4; ++r) acc[i][j][r] = 0.f;

        const uint32_t bs = b_base + stage * STAGE;
        #pragma unroll
        for (int ks = 0; ks < 4; ++ks) {
            uint32_t bh[4][2];
            {
                uint32_t r0[4], r1[4];
                ldsm_x4(r0, bs + ks * 32);
                ldsm_x4(r1, bs + 16 * ROWB + ks * 32);
                bh[0][0] = r0[0]; bh[0][1] = r0[1];
                bh[1][0] = r0[2]; bh[1][1] = r0[3];
                bh[2][0] = r1[0]; bh[2][1] = r1[1];
                bh[3][0] = r1[2]; bh[3][1] = r1[3];
            }
            #pragma unroll
            for (int i = 0; i < 4; ++i)
                #pragma unroll
                for (int j = 0; j < 4; ++j) mma16816(acc[i][j], af[ks][i], bh[j]);
        }

        // ---- fused argmin epilogue (top-3 per owned query row) ----
        const int kb = t * NT;
        #pragma unroll
        for (int j = 0; j < 4; ++j) {
            float2 cs = *(const float2*)(smem + SM_B + stage * STAGE + TERM_BYTES
                        + (warp_n * 32 + j * 8 + (lane & 3) * 2) * 4);
            const int k0 = kb + warp_n * 32 + j * 8 + (lane & 3) * 2;
            #pragma unroll
            for (int i = 0; i < 4; ++i) {
                #pragma unroll
                for (int h = 0; h < 2; ++h) {
                    const int ri = i * 2 + h;
                    #pragma unroll
                    for (int c = 0; c < 2; ++c) {
                        float m = fmaf(-2.f, acc[i][j][h * 2 + c], c ? cs.y : cs.x);
                        const int k = k0 + c;
                        if (m < bm3[ri]) {
                            if (m < bm1[ri]) {
                                bm3[ri] = bm2[ri]; bi3[ri] = bi2[ri];
                                bm2[ri] = bm1[ri]; bi2[ri] = bi1[ri];
                                bm1[ri] = m;       bi1[ri] = k;
                            } else if (m < bm2[ri]) {
                                bm3[ri] = bm2[ri]; bi3[ri] = bi2[ri];
                                bm2[ri] = m;       bi2[ri] = k;
                            } else {
                                bm3[ri] = m;       bi3[ri] = k;
                            }
                        }
                    }
                }
            }
        }
        // next iteration's leading sync protects stage reuse
    }

    // ---- candidate dump: 16 slices x 3 (m, k) per query ----
    __syncthreads();
    {
        float2* cand = (float2*)(smem + SM_CAND);
        const int slot = warp_n * 4 + (lane & 3);        // 0..15
        #pragma unroll
        for (int i = 0; i < 4; ++i)
            #pragma unroll
            for (int h = 0; h < 2; ++h) {
                const int ri = i * 2 + h;
                const int q  = warp_m * 64 + i * 16 + h * 8 + (lane >> 2);
                float2* p = &cand[q * 48 + slot * 3];
                p[0] = make_float2(bm1[ri], __int_as_float(bi1[ri]));
                p[1] = make_float2(bm2[ri], __int_as_float(bi2[ri]));
                p[2] = make_float2(bm3[ri], __int_as_float(bi3[ri]));
            }
    }
    __syncthreads();

    // ---- margin-gated exact fp32 rescore: one warp per query ----
    {
        const float2* cand = (const float2*)(smem + SM_CAND);
        int* bestk = (int*)(smem + SM_BESTK);
        for (int it = 0; it < 16; ++it) {
            const int q = wid * 16 + it;
            // round 0: slots 0..31, round 1: slots 32..47 (lane < 16)
            float2 c0 = cand[q * 48 + lane];
            float2 c1 = (lane < 16) ? cand[q * 48 + 32 + lane]
                                    : make_float2(3.4e38f, __int_as_float(0));
            // approximate minimum across all 48 candidates
            float lm = fminf(c0.x, c1.x);
            #pragma unroll
            for (int off = 16; off; off >>= 1)
                lm = fminf(lm, __shfl_xor_sync(0xffffffffu, lm, off));
            const float thresh = lm + TAU;

            const float4* er = (const float4*)(enc + (size_t)(m0 + q) * DIMS);
            float bm = 3.4e38f; int bk = 0x7fffffff;
            #pragma unroll
            for (int rnd = 0; rnd < 2; ++rnd) {
                float2 cc = rnd ? c1 : c0;
                if (cc.x <= thresh) {
                    const int k = __float_as_int(cc.y);
                    const float4* cr = (const float4*)(cb + (size_t)k * DIMS);
                    float s = 0.f;
                    #pragma unroll
                    for (int u = 0; u < 16; ++u) {
                        float4 a = er[u], b = cr[u];
                        s = fmaf(a.x, b.x, s); s = fmaf(a.y, b.y, s);
                        s = fmaf(a.z, b.z, s); s = fmaf(a.w, b.w, s);
                    }
                    float m = fmaf(-2.f, s, g_csq[k]);
                    if (m < bm || (m == bm && k < bk)) { bm = m; bk = k; }
                }
            }
            // warp argmin with first-occurrence (smallest k) tie-break
            #pragma unroll
            for (int off = 16; off; off >>= 1) {
                float om = __shfl_xor_sync(0xffffffffu, bm, off);
                int   ok = __shfl_xor_sync(0xffffffffu, bk, off);
                if (om < bm || (om == bm && ok < bk)) { bm = om; bk = ok; }
            }
            if (lane == 0) bestk[q] = bk;
        }
    }
    __syncthreads();

    // ---- gather output rows ----
    {
        const int* bestk = (const int*)(smem + SM_BESTK);
        const float4* cb4 = (const float4*)cb;
        float4* out4 = (float4*)out;
        #pragma unroll
        for (int i = 0; i < 8; ++i) {
            int lin = tid + i * THREADS;            // 0..2047
            int q = lin >> 4;
            int quad = lin & 15;
            out4[(size_t)(m0 + q) * 16 + quad] = cb4[(size_t)bestk[q] * 16 + quad];
        }
    }
}

extern "C" void kernel_launch(void* const* d_in, const int* in_sizes, int n_in,
                              void* d_out, int out_size) {
    const float* enc = (const float*)d_in[0];
    const float* cb  = (const float*)d_in[1];
    if (n_in >= 2 && in_sizes[0] == K_CB * DIMS && in_sizes[1] == N_Q * DIMS) {
        enc = (const float*)d_in[1];
        cb  = (const float*)d_in[0];
    }
    float* out = (float*)d_out;

    cudaFuncSetAttribute(vq_main, cudaFuncAttributeMaxDynamicSharedMemorySize, SMEM_TOTAL);

    prep_kernel<<<(N_Q * DIMS + K_CB * DIMS) / 4 / 256, 256>>>(enc, cb);
    csq_kernel<<<K_CB / 8, 256>>>(cb);
    vq_main<<<N_Q / MT, THREADS, SMEM_TOTAL>>>(enc, cb, out);
}

// round 8
// speedup vs baseline: 3.7405x; 1.3281x over previous
#include <cuda_runtime.h>
#include <cuda_bf16.h>
#include <cstdint>

#define N_Q   16384
#define DIMS  64
#define K_CB  8192
#define MT    128            // queries per CTA
#define NT    128            // codewords per tile
#define NTILES (K_CB / NT)   // 64
#define THREADS 512

// padded bf16 row: 64 elems + 8 pad = 72 elems = 144 bytes
#define ROWB 144
#define TERM_BYTES (128 * ROWB)      // 18432 per tile (128 rows)
#define STAGE (TERM_BYTES + 512)     // tile + csq = 18944
#define TAU 2.0f

// shared memory layout (bytes)
#define SM_B     0                       // 4 stages x 18944 = 75776
#define SM_A     75776                   // 18432
#define SM_CAND  94208                   // 128 q x 48 slots x 8B = 49152
#define SM_BESTK 143360                  // 128 ints
#define SMEM_TOTAL 143872

__device__ __nv_bfloat16 g_enc_bf[N_Q * DIMS];
__device__ __nv_bfloat16 g_cb_bf[K_CB * DIMS];
__device__ __align__(16) float g_csq[K_CB];

// ---------------- helpers ----------------
__device__ __forceinline__ uint32_t smem_u32(const void* p) {
    uint32_t a;
    asm("{ .reg .u64 t; cvta.to.shared.u64 t, %1; cvt.u32.u64 %0, t; }" : "=r"(a) : "l"(p));
    return a;
}
#define CP16(d, s)  asm volatile("cp.async.cg.shared.global [%0], [%1], 16;" :: "r"(d), "l"(s))
#define CP_COMMIT() asm volatile("cp.async.commit_group;" ::: "memory")
#define CP_WAIT2()  asm volatile("cp.async.wait_group 2;" ::: "memory")

__device__ __forceinline__ void ldsm_x4(uint32_t* r, uint32_t addr) {
    asm volatile("ldmatrix.sync.aligned.m8n8.x4.shared.b16 {%0,%1,%2,%3}, [%4];"
                 : "=r"(r[0]), "=r"(r[1]), "=r"(r[2]), "=r"(r[3]) : "r"(addr));
}
__device__ __forceinline__ void mma16816(float* c, const uint32_t* a, const uint32_t* b) {
    asm volatile("mma.sync.aligned.m16n8k16.row.col.f32.bf16.bf16.f32 "
                 "{%0,%1,%2,%3}, {%4,%5,%6,%7}, {%8,%9}, {%0,%1,%2,%3};"
                 : "+f"(c[0]), "+f"(c[1]), "+f"(c[2]), "+f"(c[3])
                 : "r"(a[0]), "r"(a[1]), "r"(a[2]), "r"(a[3]), "r"(b[0]), "r"(b[1]));
}

// ---------------- preprocessing ----------------
__global__ void prep_kernel(const float* __restrict__ enc, const float* __restrict__ cb) {
    int idx = blockIdx.x * blockDim.x + threadIdx.x;     // one float4
    const int n4e = N_Q * DIMS / 4;
    const float4* src;
    __nv_bfloat162* ph;
    int j;
    if (idx < n4e) { src = (const float4*)enc; j = idx; ph = (__nv_bfloat162*)g_enc_bf; }
    else           { src = (const float4*)cb;  j = idx - n4e; ph = (__nv_bfloat162*)g_cb_bf; }
    float4 v = src[j];
    __nv_bfloat162 a; a.x = __float2bfloat16(v.x); a.y = __float2bfloat16(v.y);
    __nv_bfloat162 b; b.x = __float2bfloat16(v.z); b.y = __float2bfloat16(v.w);
    ph[j * 2] = a; ph[j * 2 + 1] = b;
}

__global__ void csq_kernel(const float* __restrict__ cb) {
    int row  = blockIdx.x * 8 + (threadIdx.x >> 5);
    int lane = threadIdx.x & 31;
    float v0 = cb[row * DIMS + lane];
    float v1 = cb[row * DIMS + 32 + lane];
    float s  = v0 * v0 + v1 * v1;
    #pragma unroll
    for (int off = 16; off; off >>= 1) s += __shfl_xor_sync(0xffffffffu, s, off);
    if (lane == 0) g_csq[row] = s;
}

// ---------------- B tile loader ----------------
__device__ __forceinline__ void load_B_tile(uint32_t smem_base, int tile, int stage, int tid) {
    const int kb = tile * NT;
    #pragma unroll
    for (int i = 0; i < 2; ++i) {
        int c = tid + i * THREADS;        // 0..1023
        int r = c >> 3;                   // codeword row within tile
        int q = c & 7;                    // 16B chunk
        const char* src = (const char*)g_cb_bf + (size_t)(kb + r) * 128 + q * 16;
        uint32_t dst = smem_base + SM_B + stage * STAGE + r * ROWB + q * 16;
        CP16(dst, src);
    }
    if (tid < 32) {
        uint32_t dst = smem_base + SM_B + stage * STAGE + TERM_BYTES + tid * 16;
        CP16(dst, (const char*)g_csq + (size_t)kb * 4 + tid * 16);
    }
}

// ---------------- main kernel ----------------
__global__ __launch_bounds__(THREADS, 1)
void vq_main(const float* __restrict__ enc, const float* __restrict__ cb,
             float* __restrict__ out)
{
    extern __shared__ char smem[];
    const uint32_t smem_base = smem_u32(smem);
    const int tid  = threadIdx.x;
    const int wid  = tid >> 5;
    const int lane = tid & 31;
    const int wm   = wid & 3;             // 4 warps over M (32 rows each)
    const int wn   = wid >> 2;            // 4 warps over N (32 cols each)
    const int m0   = blockIdx.x * MT;

    // ---- start B pipeline immediately (stages 0..2) ----
    load_B_tile(smem_base, 0, 0, tid); CP_COMMIT();
    load_B_tile(smem_base, 1, 1, tid); CP_COMMIT();
    load_B_tile(smem_base, 2, 2, tid); CP_COMMIT();

    // ---- stage A (bf16), padded rows ----
    #pragma unroll
    for (int i = 0; i < 2; ++i) {
        int c = tid + i * THREADS;        // 0..1023
        int r = c >> 3;
        int q = c & 7;
        const uint4* src = (const uint4*)(g_enc_bf + (size_t)(m0 + r) * DIMS) + q;
        *(uint4*)(smem + SM_A + r * ROWB + q * 16) = *src;
    }
    __syncthreads();

    // ldmatrix base addresses
    const uint32_t a_base = smem_base + SM_A
        + (wm * 32 + (lane & 15)) * ROWB + ((lane >> 4) & 1) * 16;
    const uint32_t b_base = smem_base + SM_B
        + (wn * 32 + (lane >> 4) * 8 + (lane & 7)) * ROWB + ((lane >> 3) & 1) * 16;

    // ---- hoist A fragments (tile-invariant): 2 m16 tiles x 4 ks ----
    uint32_t af[4][2][4];                 // [ks][i][frag]
    #pragma unroll
    for (int ks = 0; ks < 4; ++ks)
        #pragma unroll
        for (int i = 0; i < 2; ++i)
            ldsm_x4(af[ks][i], a_base + i * 16 * ROWB + ks * 32);

    // top-3 per owned query row (4 rows/thread)
    float bm1[4], bm2[4], bm3[4];
    int   bi1[4], bi2[4], bi3[4];
    #pragma unroll
    for (int r = 0; r < 4; ++r) {
        bm1[r] = 3.4e38f; bm2[r] = 3.4e38f; bm3[r] = 3.4e38f;
        bi1[r] = 0; bi2[r] = 0; bi3[r] = 0;
    }

    float acc[2][4][4];

    for (int t = 0; t < NTILES; ++t) {
        const int stage = t & 3;
        CP_WAIT2();                       // tile t resident
        __syncthreads();                  // stage (t+3)&3 fully consumed by all warps
        if (t + 3 < NTILES) load_B_tile(smem_base, t + 3, (t + 3) & 3, tid);
        CP_COMMIT();

        #pragma unroll
        for (int i = 0; i < 2; ++i)
            #pragma unroll
            for (int j = 0; j < 4; ++j)
                #pragma unroll
                for (int r = 0; r < 4; ++r) acc[i][j][r] = 0.f;

        const uint32_t bs = b_base + stage * STAGE;
        #pragma unroll
        for (int ks = 0; ks < 4; ++ks) {
            uint32_t bh[4][2];
            {
                uint32_t r0[4], r1[4];
                ldsm_x4(r0, bs + ks * 32);
                ldsm_x4(r1, bs + 16 * ROWB + ks * 32);
                bh[0][0] = r0[0]; bh[0][1] = r0[1];
                bh[1][0] = r0[2]; bh[1][1] = r0[3];
                bh[2][0] = r1[0]; bh[2][1] = r1[1];
                bh[3][0] = r1[2]; bh[3][1] = r1[3];
            }
            #pragma unroll
            for (int i = 0; i < 2; ++i)
                #pragma unroll
                for (int j = 0; j < 4; ++j) mma16816(acc[i][j], af[ks][i], bh[j]);
        }

        // ---- fused argmin epilogue (top-3 per owned query row) ----
        const int kb = t * NT;
        #pragma unroll
        for (int j = 0; j < 4; ++j) {
            float2 cs = *(const float2*)(smem + SM_B + stage * STAGE + TERM_BYTES
                        + (wn * 32 + j * 8 + (lane & 3) * 2) * 4);
            const int k0 = kb + wn * 32 + j * 8 + (lane & 3) * 2;
            #pragma unroll
            for (int i = 0; i < 2; ++i) {
                #pragma unroll
                for (int h = 0; h < 2; ++h) {
                    const int ri = i * 2 + h;
                    #pragma unroll
                    for (int c = 0; c < 2; ++c) {
                        float m = fmaf(-2.f, acc[i][j][h * 2 + c], c ? cs.y : cs.x);
                        const int k = k0 + c;
                        if (m < bm3[ri]) {
                            if (m < bm1[ri]) {
                                bm3[ri] = bm2[ri]; bi3[ri] = bi2[ri];
                                bm2[ri] = bm1[ri]; bi2[ri] = bi1[ri];
                                bm1[ri] = m;       bi1[ri] = k;
                            } else if (m < bm2[ri]) {
                                bm3[ri] = bm2[ri]; bi3[ri] = bi2[ri];
                                bm2[ri] = m;       bi2[ri] = k;
                            } else {
                                bm3[ri] = m;       bi3[ri] = k;
                            }
                        }
                    }
                }
            }
        }
        // next iteration's leading sync protects stage reuse
    }

    // ---- candidate dump: 16 slices x 3 (m, k) per query ----
    __syncthreads();
    {
        float2* cand = (float2*)(smem + SM_CAND);
        const int slot = wn * 4 + (lane & 3);            // 0..15
        #pragma unroll
        for (int i = 0; i < 2; ++i)
            #pragma unroll
            for (int h = 0; h < 2; ++h) {
                const int ri = i * 2 + h;
                const int q  = wm * 32 + i * 16 + h * 8 + (lane >> 2);
                float2* p = &cand[q * 48 + slot * 3];
                p[0] = make_float2(bm1[ri], __int_as_float(bi1[ri]));
                p[1] = make_float2(bm2[ri], __int_as_float(bi2[ri]));
                p[2] = make_float2(bm3[ri], __int_as_float(bi3[ri]));
            }
    }
    __syncthreads();

    // ---- margin-gated exact fp32 rescore: one warp per query ----
    {
        const float2* cand = (const float2*)(smem + SM_CAND);
        int* bestk = (int*)(smem + SM_BESTK);
        for (int it = 0; it < 8; ++it) {
            const int q = wid * 8 + it;
            // round 0: slots 0..31, round 1: slots 32..47 (lane < 16)
            float2 c0 = cand[q * 48 + lane];
            float2 c1 = (lane < 16) ? cand[q * 48 + 32 + lane]
                                    : make_float2(3.4e38f, __int_as_float(0));
            float lm = fminf(c0.x, c1.x);
            #pragma unroll
            for (int off = 16; off; off >>= 1)
                lm = fminf(lm, __shfl_xor_sync(0xffffffffu, lm, off));
            const float thresh = lm + TAU;

            const float4* er = (const float4*)(enc + (size_t)(m0 + q) * DIMS);
            float bm = 3.4e38f; int bk = 0x7fffffff;
            #pragma unroll
            for (int rnd = 0; rnd < 2; ++rnd) {
                float2 cc = rnd ? c1 : c0;
                if (cc.x <= thresh) {
                    const int k = __float_as_int(cc.y);
                    const float4* cr = (const float4*)(cb + (size_t)k * DIMS);
                    float s = 0.f;
                    #pragma unroll
                    for (int u = 0; u < 16; ++u) {
                        float4 a = er[u], b = cr[u];
                        s = fmaf(a.x, b.x, s); s = fmaf(a.y, b.y, s);
                        s = fmaf(a.z, b.z, s); s = fmaf(a.w, b.w, s);
                    }
                    float m = fmaf(-2.f, s, g_csq[k]);
                    if (m < bm || (m == bm && k < bk)) { bm = m; bk = k; }
                }
            }
            #pragma unroll
            for (int off = 16; off; off >>= 1) {
                float om = __shfl_xor_sync(0xffffffffu, bm, off);
                int   ok = __shfl_xor_sync(0xffffffffu, bk, off);
                if (om < bm || (om == bm && ok < bk)) { bm = om; bk = ok; }
            }
            if (lane == 0) bestk[q] = bk;
        }
    }
    __syncthreads();

    // ---- gather output rows ----
    {
        const int* bestk = (const int*)(smem + SM_BESTK);
        const float4* cb4 = (const float4*)cb;
        float4* out4 = (float4*)out;
        #pragma unroll
        for (int i = 0; i < 4; ++i) {
            int lin = tid + i * THREADS;            // 0..2047
            int q = lin >> 4;
            int quad = lin & 15;
            out4[(size_t)(m0 + q) * 16 + quad] = cb4[(size_t)bestk[q] * 16 + quad];
        }
    }
}

extern "C" void kernel_launch(void* const* d_in, const int* in_sizes, int n_in,
                              void* d_out, int out_size) {
    const float* enc = (const float*)d_in[0];
    const float* cb  = (const float*)d_in[1];
    if (n_in >= 2 && in_sizes[0] == K_CB * DIMS && in_sizes[1] == N_Q * DIMS) {
        enc = (const float*)d_in[1];
        cb  = (const float*)d_in[0];
    }
    float* out = (float*)d_out;

    cudaFuncSetAttribute(vq_main, cudaFuncAttributeMaxDynamicSharedMemorySize, SMEM_TOTAL);

    prep_kernel<<<(N_Q * DIMS + K_CB * DIMS) / 4 / 256, 256>>>(enc, cb);
    csq_kernel<<<K_CB / 8, 256>>>(cb);
    vq_main<<<N_Q / MT, THREADS, SMEM_TOTAL>>>(enc, cb, out);
}